// round 8
// baseline (speedup 1.0000x reference)
#include <cuda_runtime.h>
#include <cuda_fp16.h>

#define NN 100000
#define NE 3200000
#define F1 16
#define CAP 96                       // slots per node (Poisson(32): overflow ~0)
#define OVF_MAX (1 << 20)

#define GEMM_BLKS 196                // 196 * 512 nodes
#define FILL_BLKS (NE / 4 / 256)     // 3125 (4 edges per thread)

// ---- static device scratch (no cudaMalloc allowed) ----
__device__ float  g_h0f[NN * F1];    // (x @ W1) [* dinv after k_scale], fp32
__device__ float  g_gs[NN];          // layer-1 output * dinv[node]
__device__ float  g_dinv[NN];
__device__ int    g_csr[NN * CAP];   // padded bins: src, grouped by dst
__device__ int    g_is64;

// zeroed each launch with ONE memset (prefix only)
__device__ struct {
    int cursor[NN];
    int ovf_cnt;
    int2 ovf[OVF_MAX];               // NOT memset (only first ovf_cnt valid)
} g_dyn;

// ---------------- dtype detect (int64 vs int32 edge_index) -----------------
__global__ void k_detect(const unsigned int* __restrict__ ei32) {
    if (threadIdx.x == 0) {
        int ok = 1;
        #pragma unroll 1
        for (int k = 0; k < 64; k++)
            if (ei32[2 * k + 1] != 0u) { ok = 0; break; }
        g_is64 = ok;
    }
}

// ---------------- fused: GEMM1 + CSR bin-fill (independent work) -----------
__global__ __launch_bounds__(256) void k_fill_gemm(
    const float* __restrict__ x, const float* __restrict__ W1,
    const void* __restrict__ ei) {
    if (blockIdx.x >= GEMM_BLKS) {
        // ---- fill: 4 edges/thread ----
        int base = ((blockIdx.x - GEMM_BLKS) * 256 + threadIdx.x) * 4;
        int r[4], c[4];
        if (g_is64) {
            const int4* p = (const int4*)ei;            // row half
            const int4* q = (const int4*)ei + NE / 2;   // col half
            int4 a = __ldg(p + base / 2);
            int4 b = __ldg(p + base / 2 + 1);
            int4 d = __ldg(q + base / 2);
            int4 e = __ldg(q + base / 2 + 1);
            r[0] = a.x; r[1] = a.z; r[2] = b.x; r[3] = b.z;
            c[0] = d.x; c[1] = d.z; c[2] = e.x; c[3] = e.z;
        } else {
            int4 a = __ldg((const int4*)((const int*)ei) + base / 4);
            int4 d = __ldg((const int4*)((const int*)ei + NE) + base / 4);
            r[0] = a.x; r[1] = a.y; r[2] = a.z; r[3] = a.w;
            c[0] = d.x; c[1] = d.y; c[2] = d.z; c[3] = d.w;
        }
        int s[4];
        #pragma unroll
        for (int j = 0; j < 4; j++) s[j] = atomicAdd(&g_dyn.cursor[c[j]], 1);
        #pragma unroll
        for (int j = 0; j < 4; j++) {
            if (s[j] < CAP) {
                g_csr[c[j] * CAP + s[j]] = r[j];
            } else {                      // guaranteed-correct spill path
                int o = atomicAdd(&g_dyn.ovf_cnt, 1);
                if (o < OVF_MAX) g_dyn.ovf[o] = make_int2(r[j], c[j]);
            }
        }
        return;
    }
    // ---- GEMM: h0f = x @ W1, fp32, unscaled ----
    __shared__ float ws[128 * F1];
    for (int t = threadIdx.x; t < 128 * F1; t += 256) ws[t] = W1[t];
    __syncthreads();

    int nbase = blockIdx.x * 512 + threadIdx.x;
    float acc[2][F1];
    #pragma unroll
    for (int nn = 0; nn < 2; nn++)
        #pragma unroll
        for (int j = 0; j < F1; j++) acc[nn][j] = 0.0f;

    #pragma unroll 4
    for (int k4 = 0; k4 < 32; k4++) {
        float4 xr[2];
        #pragma unroll
        for (int nn = 0; nn < 2; nn++) {
            int node = nbase + nn * 256;
            xr[nn] = (node < NN)
                ? __ldg((const float4*)(x + (long long)node * 128) + k4)
                : make_float4(0.f, 0.f, 0.f, 0.f);
        }
        #pragma unroll
        for (int kk = 0; kk < 4; kk++) {
            #pragma unroll
            for (int j = 0; j < F1; j++) {
                float wv = ws[(k4 * 4 + kk) * F1 + j];
                #pragma unroll
                for (int nn = 0; nn < 2; nn++) {
                    const float* xa = (const float*)&xr[nn];
                    acc[nn][j] = fmaf(xa[kk], wv, acc[nn][j]);
                }
            }
        }
    }
    #pragma unroll
    for (int nn = 0; nn < 2; nn++) {
        int node = nbase + nn * 256;
        if (node < NN) {
            float4* o = (float4*)(g_h0f + (long long)node * F1);
            o[0] = make_float4(acc[nn][0], acc[nn][1], acc[nn][2], acc[nn][3]);
            o[1] = make_float4(acc[nn][4], acc[nn][5], acc[nn][6], acc[nn][7]);
            o[2] = make_float4(acc[nn][8], acc[nn][9], acc[nn][10], acc[nn][11]);
            o[3] = make_float4(acc[nn][12], acc[nn][13], acc[nn][14], acc[nn][15]);
        }
    }
}

// ---------------- scale: dinv from cursor counts; h0f *= dinv --------------
__global__ __launch_bounds__(256) void k_scale() {
    int i = blockIdx.x * 256 + threadIdx.x;
    if (i >= NN) return;
    int cnt = g_dyn.cursor[i];
    float di = rsqrtf((float)cnt + 1.0f);
    g_dinv[i] = di;
    float4* row = (float4*)(g_h0f + (long long)i * F1);
    #pragma unroll
    for (int j = 0; j < 4; j++) {
        float4 v = row[j];
        row[j] = make_float4(v.x * di, v.y * di, v.z * di, v.w * di);
    }
}

// ---------------- gather1: warp/node, 16 edges/iter, predicate-free --------
// q = lane>>2 selects edge slot, f4 = lane&3 selects 16B quarter of h0f row
__global__ __launch_bounds__(256) void k_gather1(
    const float* __restrict__ b1, const float* __restrict__ W2) {
    int node = (blockIdx.x * blockDim.x + threadIdx.x) >> 5;
    int lane = threadIdx.x & 31;
    if (node >= NN) return;
    int cnt = g_dyn.cursor[node];
    int len = min(cnt, CAP);
    const int* bin = g_csr + node * CAP;
    int q  = lane >> 2;
    int f4 = lane & 3;

    // init with self-loop (h0f already dinv-scaled) on edge-slot 0
    float4 accA = make_float4(0.f, 0.f, 0.f, 0.f);
    float4 accB = make_float4(0.f, 0.f, 0.f, 0.f);
    if (q == 0)
        accA = __ldg((const float4*)(g_h0f + (long long)node * F1) + f4);

    int main_end = len & ~15;                 // full 16-edge chunks
    for (int p = 0; p < main_end; p += 16) {  // NO predicates in main loop
        int s0 = __ldg(bin + p + q);
        int s1 = __ldg(bin + p + q + 8);
        float4 v0 = __ldg((const float4*)(g_h0f + (long long)s0 * F1) + f4);
        float4 v1 = __ldg((const float4*)(g_h0f + (long long)s1 * F1) + f4);
        accA.x += v0.x; accA.y += v0.y; accA.z += v0.z; accA.w += v0.w;
        accB.x += v1.x; accB.y += v1.y; accB.z += v1.z; accB.w += v1.w;
    }
    // tail: up to 15 edges, 8 at a time predicated
    for (int p = main_end; p < len; p += 8) {
        int idx = p + q;
        if (idx < len) {
            int src = __ldg(bin + idx);
            float4 v = __ldg((const float4*)(g_h0f + (long long)src * F1) + f4);
            accB.x += v.x; accB.y += v.y; accB.z += v.z; accB.w += v.w;
        }
    }
    accA.x += accB.x; accA.y += accB.y; accA.z += accB.z; accA.w += accB.w;

    // reduce across the 8 edge-slots (keep f4 split)
    #pragma unroll
    for (int off = 4; off < 32; off <<= 1) {
        accA.x += __shfl_xor_sync(0xffffffffu, accA.x, off);
        accA.y += __shfl_xor_sync(0xffffffffu, accA.y, off);
        accA.z += __shfl_xor_sync(0xffffffffu, accA.z, off);
        accA.w += __shfl_xor_sync(0xffffffffu, accA.w, off);
    }
    float di = __ldg(&g_dinv[node]);
    float v = 0.0f;
    if (lane < 4) {
        if (cnt > CAP) {    // overflow path (never taken for this input)
            int no = min(g_dyn.ovf_cnt, OVF_MAX);
            for (int o = 0; o < no; o++) {
                int2 rc = g_dyn.ovf[o];
                if (rc.y == node) {
                    float4 u = __ldg((const float4*)(g_h0f + (long long)rc.x * F1) + f4);
                    accA.x += u.x; accA.y += u.y; accA.z += u.z; accA.w += u.w;
                }
            }
        }
        float4 bb = __ldg((const float4*)b1 + lane);
        float4 ww = __ldg((const float4*)W2 + lane);
        float t0 = fmaxf(fmaf(accA.x, di, bb.x), 0.f) * ww.x;
        float t1 = fmaxf(fmaf(accA.y, di, bb.y), 0.f) * ww.y;
        float t2 = fmaxf(fmaf(accA.z, di, bb.z), 0.f) * ww.z;
        float t3 = fmaxf(fmaf(accA.w, di, bb.w), 0.f) * ww.w;
        v = (t0 + t1) + (t2 + t3);
    }
    v += __shfl_xor_sync(0xffffffffu, v, 1);
    v += __shfl_xor_sync(0xffffffffu, v, 2);
    if (lane == 0) g_gs[node] = v * di;
}

// ---------------- gather2: int4 csr loads, 4 edges/lane/iter ---------------
__global__ __launch_bounds__(256) void k_gather2(
    const float* __restrict__ b2, float* __restrict__ out) {
    int node = (blockIdx.x * blockDim.x + threadIdx.x) >> 5;
    int lane = threadIdx.x & 31;
    if (node >= NN) return;
    int cnt = g_dyn.cursor[node];
    int len = min(cnt, CAP);
    const int* bin = g_csr + node * CAP;   // CAP%4==0: bins int4-aligned

    float acc = 0.0f;
    int main_end = len & ~3;               // full int4 groups
    for (int p = lane * 4; p < main_end; p += 128) {
        int4 s = __ldg((const int4*)(bin + p));
        acc += __ldg(&g_gs[s.x]) + __ldg(&g_gs[s.y])
             + __ldg(&g_gs[s.z]) + __ldg(&g_gs[s.w]);
    }
    // tail (<4 edges) + self loop
    if (lane < 4) {
        int idx = main_end + lane;
        if (idx < len) acc += __ldg(&g_gs[__ldg(bin + idx)]);
    }
    if (lane == 0) {
        acc += __ldg(&g_gs[node]);   // self loop
        if (cnt > CAP) {             // overflow path (never taken here)
            int no = min(g_dyn.ovf_cnt, OVF_MAX);
            for (int o = 0; o < no; o++) {
                int2 rc = g_dyn.ovf[o];
                if (rc.y == node) acc += __ldg(&g_gs[rc.x]);
            }
        }
    }

    acc += __shfl_xor_sync(0xffffffffu, acc, 16);
    acc += __shfl_xor_sync(0xffffffffu, acc, 8);
    acc += __shfl_xor_sync(0xffffffffu, acc, 4);
    acc += __shfl_xor_sync(0xffffffffu, acc, 2);
    acc += __shfl_xor_sync(0xffffffffu, acc, 1);
    if (lane == 0) {
        float v = fmaf(acc, __ldg(&g_dinv[node]), __ldg(&b2[0]));
        out[node] = 1.0f / (1.0f + __expf(-v));
    }
}

// ---------------- launch ----------------------------------------------------
extern "C" void kernel_launch(void* const* d_in, const int* in_sizes, int n_in,
                              void* d_out, int out_size) {
    const float* x  = (const float*)d_in[0];
    const void*  ei = d_in[1];
    const float* W1 = (const float*)d_in[2];
    const float* b1 = (const float*)d_in[3];
    const float* W2 = (const float*)d_in[4];
    const float* b2 = (const float*)d_in[5];
    float* out = (float*)d_out;

    static void* dyn_addr = nullptr;
    if (!dyn_addr) cudaGetSymbolAddress(&dyn_addr, g_dyn);

    // zero cursors + ovf_cnt only (prefix of g_dyn)
    cudaMemsetAsync(dyn_addr, 0, (size_t)(NN + 1) * sizeof(int));
    k_detect<<<1, 32>>>((const unsigned int*)ei);
    k_fill_gemm<<<GEMM_BLKS + FILL_BLKS, 256>>>(x, W1, ei);
    k_scale<<<(NN + 255) / 256, 256>>>();
    k_gather1<<<(NN * 32 + 255) / 256, 256>>>(b1, W2);
    k_gather2<<<(NN * 32 + 255) / 256, 256>>>(b2, out);
}

// round 9
// speedup vs baseline: 1.0649x; 1.0649x over previous
#include <cuda_runtime.h>
#include <cuda_fp16.h>

#define NN 100000
#define NE 3200000
#define F1 16
#define CAP 64                       // slots per node (Poisson(32): P(>64)~4e-6/node; spill path handles rest)
#define OVF_MAX (1 << 20)

#define GEMM_BLKS 196                // 196 * 512 nodes
#define FILL_BLKS (NE / 4 / 256)     // 3125 (4 edges per thread)

// ---- static device scratch (no cudaMalloc allowed) ----
__device__ float  g_h0f[NN * F1];    // (x @ W1) [* dinv after k_scale], fp32
__device__ float  g_gs[NN];          // layer-1 output * dinv[node]
__device__ float  g_dinv[NN];
__device__ int    g_csr[NN * CAP];   // padded bins: src, grouped by dst
__device__ int    g_is64;

// zeroed each launch with ONE memset (prefix only)
__device__ struct {
    int cursor[NN];
    int ovf_cnt;
    int2 ovf[OVF_MAX];               // NOT memset (only first ovf_cnt valid)
} g_dyn;

// ---------------- dtype detect (int64 vs int32 edge_index) -----------------
__global__ void k_detect(const unsigned int* __restrict__ ei32) {
    if (threadIdx.x == 0) {
        int ok = 1;
        #pragma unroll 1
        for (int k = 0; k < 64; k++)
            if (ei32[2 * k + 1] != 0u) { ok = 0; break; }
        g_is64 = ok;
    }
}

// ---------------- fused: GEMM1 + CSR bin-fill (independent work) -----------
__global__ __launch_bounds__(256) void k_fill_gemm(
    const float* __restrict__ x, const float* __restrict__ W1,
    const void* __restrict__ ei) {
    if (blockIdx.x >= GEMM_BLKS) {
        // ---- fill: 4 edges/thread ----
        int base = ((blockIdx.x - GEMM_BLKS) * 256 + threadIdx.x) * 4;
        int r[4], c[4];
        if (g_is64) {
            const int4* p = (const int4*)ei;            // row half
            const int4* q = (const int4*)ei + NE / 2;   // col half
            int4 a = __ldg(p + base / 2);
            int4 b = __ldg(p + base / 2 + 1);
            int4 d = __ldg(q + base / 2);
            int4 e = __ldg(q + base / 2 + 1);
            r[0] = a.x; r[1] = a.z; r[2] = b.x; r[3] = b.z;
            c[0] = d.x; c[1] = d.z; c[2] = e.x; c[3] = e.z;
        } else {
            int4 a = __ldg((const int4*)((const int*)ei) + base / 4);
            int4 d = __ldg((const int4*)((const int*)ei + NE) + base / 4);
            r[0] = a.x; r[1] = a.y; r[2] = a.z; r[3] = a.w;
            c[0] = d.x; c[1] = d.y; c[2] = d.z; c[3] = d.w;
        }
        int s[4];
        #pragma unroll
        for (int j = 0; j < 4; j++) s[j] = atomicAdd(&g_dyn.cursor[c[j]], 1);
        #pragma unroll
        for (int j = 0; j < 4; j++) {
            if (s[j] < CAP) {
                g_csr[(c[j] << 6) + s[j]] = r[j];
            } else {                      // guaranteed-correct spill path
                int o = atomicAdd(&g_dyn.ovf_cnt, 1);
                if (o < OVF_MAX) g_dyn.ovf[o] = make_int2(r[j], c[j]);
            }
        }
        return;
    }
    // ---- GEMM: h0f = x @ W1, fp32, unscaled ----
    __shared__ float ws[128 * F1];
    for (int t = threadIdx.x; t < 128 * F1; t += 256) ws[t] = W1[t];
    __syncthreads();

    int nbase = blockIdx.x * 512 + threadIdx.x;
    float acc[2][F1];
    #pragma unroll
    for (int nn = 0; nn < 2; nn++)
        #pragma unroll
        for (int j = 0; j < F1; j++) acc[nn][j] = 0.0f;

    #pragma unroll 4
    for (int k4 = 0; k4 < 32; k4++) {
        float4 xr[2];
        #pragma unroll
        for (int nn = 0; nn < 2; nn++) {
            int node = nbase + nn * 256;
            xr[nn] = (node < NN)
                ? __ldg((const float4*)(x + (long long)node * 128) + k4)
                : make_float4(0.f, 0.f, 0.f, 0.f);
        }
        #pragma unroll
        for (int kk = 0; kk < 4; kk++) {
            #pragma unroll
            for (int j = 0; j < F1; j++) {
                float wv = ws[(k4 * 4 + kk) * F1 + j];
                #pragma unroll
                for (int nn = 0; nn < 2; nn++) {
                    const float* xa = (const float*)&xr[nn];
                    acc[nn][j] = fmaf(xa[kk], wv, acc[nn][j]);
                }
            }
        }
    }
    #pragma unroll
    for (int nn = 0; nn < 2; nn++) {
        int node = nbase + nn * 256;
        if (node < NN) {
            float4* o = (float4*)(g_h0f + (long long)node * F1);
            o[0] = make_float4(acc[nn][0], acc[nn][1], acc[nn][2], acc[nn][3]);
            o[1] = make_float4(acc[nn][4], acc[nn][5], acc[nn][6], acc[nn][7]);
            o[2] = make_float4(acc[nn][8], acc[nn][9], acc[nn][10], acc[nn][11]);
            o[3] = make_float4(acc[nn][12], acc[nn][13], acc[nn][14], acc[nn][15]);
        }
    }
}

// ---------------- scale: dinv from cursor counts; h0f *= dinv --------------
__global__ __launch_bounds__(256) void k_scale() {
    int i = blockIdx.x * 256 + threadIdx.x;
    if (i >= NN) return;
    int cnt = g_dyn.cursor[i];
    float di = rsqrtf((float)cnt + 1.0f);
    g_dinv[i] = di;
    float4* row = (float4*)(g_h0f + (long long)i * F1);
    #pragma unroll
    for (int j = 0; j < 4; j++) {
        float4 v = row[j];
        row[j] = make_float4(v.x * di, v.y * di, v.z * di, v.w * di);
    }
}

// ---------------- gather1: warp/node, 4 lanes/edge, float4 (R7 shape) ------
// q = lane>>2 selects edge slot (8 per iter), f4 = lane&3 selects 16B quarter
__global__ __launch_bounds__(256) void k_gather1(
    const float* __restrict__ b1, const float* __restrict__ W2) {
    int node = (blockIdx.x * blockDim.x + threadIdx.x) >> 5;
    int lane = threadIdx.x & 31;
    if (node >= NN) return;
    int cnt = g_dyn.cursor[node];
    int len = min(cnt, CAP);
    const int* bin = g_csr + (node << 6);
    int end = len;
    int q  = lane >> 2;
    int f4 = lane & 3;

    // init with self-loop (h0f already dinv-scaled) on edge-slot 0
    float4 acc = make_float4(0.f, 0.f, 0.f, 0.f);
    if (q == 0)
        acc = __ldg((const float4*)(g_h0f + (long long)node * F1) + f4);

    for (int p = 0; p < end; p += 8) {
        int idx = p + q;
        if (idx < end) {
            int src = __ldg(bin + idx);
            float4 v = __ldg((const float4*)(g_h0f + (long long)src * F1) + f4);
            acc.x += v.x; acc.y += v.y; acc.z += v.z; acc.w += v.w;
        }
    }
    // reduce across the 8 edge-slots (keep f4 split)
    #pragma unroll
    for (int off = 4; off < 32; off <<= 1) {
        acc.x += __shfl_xor_sync(0xffffffffu, acc.x, off);
        acc.y += __shfl_xor_sync(0xffffffffu, acc.y, off);
        acc.z += __shfl_xor_sync(0xffffffffu, acc.z, off);
        acc.w += __shfl_xor_sync(0xffffffffu, acc.w, off);
    }
    float di = __ldg(&g_dinv[node]);
    float v = 0.0f;
    if (lane < 4) {
        if (cnt > CAP) {    // overflow path (correct; ~never taken)
            int no = min(g_dyn.ovf_cnt, OVF_MAX);
            for (int o = 0; o < no; o++) {
                int2 rc = g_dyn.ovf[o];
                if (rc.y == node) {
                    float4 u = __ldg((const float4*)(g_h0f + (long long)rc.x * F1) + f4);
                    acc.x += u.x; acc.y += u.y; acc.z += u.z; acc.w += u.w;
                }
            }
        }
        float4 bb = __ldg((const float4*)b1 + lane);
        float4 ww = __ldg((const float4*)W2 + lane);
        float t0 = fmaxf(fmaf(acc.x, di, bb.x), 0.f) * ww.x;
        float t1 = fmaxf(fmaf(acc.y, di, bb.y), 0.f) * ww.y;
        float t2 = fmaxf(fmaf(acc.z, di, bb.z), 0.f) * ww.z;
        float t3 = fmaxf(fmaf(acc.w, di, bb.w), 0.f) * ww.w;
        v = (t0 + t1) + (t2 + t3);
    }
    v += __shfl_xor_sync(0xffffffffu, v, 1);
    v += __shfl_xor_sync(0xffffffffu, v, 2);
    if (lane == 0) g_gs[node] = v * di;
}

// ---------------- gather2: out = sigmoid(dinv*(Σ gs + self) + b2) (R7 shape)
__global__ __launch_bounds__(256) void k_gather2(
    const float* __restrict__ b2, float* __restrict__ out) {
    int node = (blockIdx.x * blockDim.x + threadIdx.x) >> 5;
    int lane = threadIdx.x & 31;
    if (node >= NN) return;
    int cnt = g_dyn.cursor[node];
    int len = min(cnt, CAP);
    const int* bin = g_csr + (node << 6);

    float acc = 0.0f;
    int p = lane;
    for (; p + 32 < len; p += 64) {
        int s0 = __ldg(bin + p);
        int s1 = __ldg(bin + p + 32);
        acc += __ldg(&g_gs[s0]) + __ldg(&g_gs[s1]);
    }
    if (p < len) acc += __ldg(&g_gs[__ldg(bin + p)]);
    if (lane == 0) {
        acc += __ldg(&g_gs[node]);   // self loop
        if (cnt > CAP) {             // overflow path (correct; ~never taken)
            int no = min(g_dyn.ovf_cnt, OVF_MAX);
            for (int o = 0; o < no; o++) {
                int2 rc = g_dyn.ovf[o];
                if (rc.y == node) acc += __ldg(&g_gs[rc.x]);
            }
        }
    }

    acc += __shfl_xor_sync(0xffffffffu, acc, 16);
    acc += __shfl_xor_sync(0xffffffffu, acc, 8);
    acc += __shfl_xor_sync(0xffffffffu, acc, 4);
    acc += __shfl_xor_sync(0xffffffffu, acc, 2);
    acc += __shfl_xor_sync(0xffffffffu, acc, 1);
    if (lane == 0) {
        float v = fmaf(acc, __ldg(&g_dinv[node]), __ldg(&b2[0]));
        out[node] = 1.0f / (1.0f + __expf(-v));
    }
}

// ---------------- launch ----------------------------------------------------
extern "C" void kernel_launch(void* const* d_in, const int* in_sizes, int n_in,
                              void* d_out, int out_size) {
    const float* x  = (const float*)d_in[0];
    const void*  ei = d_in[1];
    const float* W1 = (const float*)d_in[2];
    const float* b1 = (const float*)d_in[3];
    const float* W2 = (const float*)d_in[4];
    const float* b2 = (const float*)d_in[5];
    float* out = (float*)d_out;

    static void* dyn_addr = nullptr;
    if (!dyn_addr) cudaGetSymbolAddress(&dyn_addr, g_dyn);

    // zero cursors + ovf_cnt only (prefix of g_dyn)
    cudaMemsetAsync(dyn_addr, 0, (size_t)(NN + 1) * sizeof(int));
    k_detect<<<1, 32>>>((const unsigned int*)ei);
    k_fill_gemm<<<GEMM_BLKS + FILL_BLKS, 256>>>(x, W1, ei);
    k_scale<<<(NN + 255) / 256, 256>>>();
    k_gather1<<<(NN * 32 + 255) / 256, 256>>>(b1, W2);
    k_gather2<<<(NN * 32 + 255) / 256, 256>>>(b2, out);
}